// round 15
// baseline (speedup 1.0000x reference)
#include <cuda_runtime.h>
#include <cuda_bf16.h>
#include <cstdint>
#include <math.h>

#define NB   4
#define NH   8
#define SEQ  2048
#define DIM  512
#define DH   64
#define MROWS (NB*SEQ)   // 8192

// =================== scratch (static device globals) ===================
__device__ float g_Q [MROWS*DIM];
__device__ float g_XK[MROWS*DIM];
__device__ float g_XV[MROWS*DIM];

__device__ __align__(16) __nv_bfloat16 g_xqh[MROWS*DIM], g_xql[MROWS*DIM];
__device__ __align__(16) __nv_bfloat16 g_xkh[MROWS*DIM], g_xkl[MROWS*DIM];
__device__ __align__(16) __nv_bfloat16 g_xvh[MROWS*DIM], g_xvl[MROWS*DIM];
__device__ __align__(16) __nv_bfloat16 g_AOh[MROWS*DIM], g_AOl[MROWS*DIM];

__device__ __align__(16) __nv_bfloat16 g_Qh [MROWS*DIM], g_Ql [MROWS*DIM];
__device__ __align__(16) __nv_bfloat16 g_Kh [MROWS*DIM], g_Kl [MROWS*DIM];
__device__ __align__(16) __nv_bfloat16 g_Vh [MROWS*DIM], g_Vl [MROWS*DIM];

__device__ __align__(16) __nv_bfloat16 g_WqTh[DIM*DIM], g_WqTl[DIM*DIM];
__device__ __align__(16) __nv_bfloat16 g_WkTh[DIM*DIM], g_WkTl[DIM*DIM];
__device__ __align__(16) __nv_bfloat16 g_WvTh[DIM*DIM], g_WvTl[DIM*DIM];
__device__ __align__(16) __nv_bfloat16 g_WoTh[DIM*DIM], g_WoTl[DIM*DIM];

// =================== helpers ===================
__device__ __forceinline__ uint32_t smem_u32(const void* p) {
    uint32_t a;
    asm("{ .reg .u64 t; cvta.to.shared.u64 t, %1; cvt.u32.u64 %0, t; }" : "=r"(a) : "l"(p));
    return a;
}

__device__ __forceinline__ void ldm_x4(uint32_t addr, uint32_t& r0, uint32_t& r1,
                                       uint32_t& r2, uint32_t& r3) {
    asm volatile("ldmatrix.sync.aligned.m8n8.x4.shared.b16 {%0,%1,%2,%3}, [%4];"
                 : "=r"(r0), "=r"(r1), "=r"(r2), "=r"(r3) : "r"(addr));
}
__device__ __forceinline__ void ldm_x4_t(uint32_t addr, uint32_t& r0, uint32_t& r1,
                                         uint32_t& r2, uint32_t& r3) {
    asm volatile("ldmatrix.sync.aligned.m8n8.x4.trans.shared.b16 {%0,%1,%2,%3}, [%4];"
                 : "=r"(r0), "=r"(r1), "=r"(r2), "=r"(r3) : "r"(addr));
}

__device__ __forceinline__ void mma_bf16(float& c0, float& c1, float& c2, float& c3,
                                         uint32_t a0, uint32_t a1, uint32_t a2, uint32_t a3,
                                         uint32_t b0, uint32_t b1) {
    asm volatile(
        "mma.sync.aligned.m16n8k16.row.col.f32.bf16.bf16.f32 "
        "{%0,%1,%2,%3}, {%4,%5,%6,%7}, {%8,%9}, {%0,%1,%2,%3};"
        : "+f"(c0), "+f"(c1), "+f"(c2), "+f"(c3)
        : "r"(a0), "r"(a1), "r"(a2), "r"(a3), "r"(b0), "r"(b1));
}

__device__ __forceinline__ void cp16(uint32_t dst, const void* src) {
    asm volatile("cp.async.cg.shared.global [%0], [%1], 16;" :: "r"(dst), "l"(src));
}
__device__ __forceinline__ void cp_commit() {
    asm volatile("cp.async.commit_group;");
}
template<int N> __device__ __forceinline__ void cp_wait() {
    asm volatile("cp.async.wait_group %0;" :: "n"(N));
}

__device__ __forceinline__ void bf16_split(float x, unsigned& h, unsigned& l) {
    __nv_bfloat16 bh = __float2bfloat16_rn(x);
    float r = x - __bfloat162float(bh);
    __nv_bfloat16 bl = __float2bfloat16_rn(r);
    h = (unsigned)__bfloat16_as_ushort(bh);
    l = (unsigned)__bfloat16_as_ushort(bl);
}
__device__ __forceinline__ float bf_lo(float x) {
    return x - __bfloat162float(__float2bfloat16_rn(x));
}
__device__ __forceinline__ uint32_t pk2(float a, float b) {
    return (uint32_t)__bfloat16_as_ushort(__float2bfloat16_rn(a)) |
           ((uint32_t)__bfloat16_as_ushort(__float2bfloat16_rn(b)) << 16);
}

// =================== conversion kernels ===================
__global__ __launch_bounds__(256) void split_hl(
    const float4* __restrict__ in, uint2* __restrict__ hi, uint2* __restrict__ lo, int n4)
{
    int i = blockIdx.x * 256 + threadIdx.x;
    if (i >= n4) return;
    float4 v = in[i];
    unsigned h0,h1,h2,h3,l0,l1,l2,l3;
    bf16_split(v.x, h0, l0); bf16_split(v.y, h1, l1);
    bf16_split(v.z, h2, l2); bf16_split(v.w, h3, l3);
    hi[i] = make_uint2(h0 | (h1 << 16), h2 | (h3 << 16));
    lo[i] = make_uint2(l0 | (l1 << 16), l2 | (l3 << 16));
}

__global__ __launch_bounds__(1024) void splitT(
    const float* __restrict__ W, __nv_bfloat16* __restrict__ hiT, __nv_bfloat16* __restrict__ loT)
{
    __shared__ float t[32][33];
    const int kb = blockIdx.y * 32, nb = blockIdx.x * 32;
    const int tx = threadIdx.x, ty = threadIdx.y;
    t[ty][tx] = W[(kb + ty) * DIM + nb + tx];
    __syncthreads();
    float x = t[tx][ty];
    unsigned h, l;
    bf16_split(x, h, l);
    hiT[(nb + ty) * DIM + kb + tx] = __ushort_as_bfloat16((unsigned short)h);
    loT[(nb + ty) * DIM + kb + tx] = __ushort_as_bfloat16((unsigned short)l);
}

// =================== HMMA GEMM: fp32 and/or bf16-hi/lo outputs ===================
#define KST   32
#define SSTR  40
#define A_EL  (128*SSTR)
#define B_EL  (256*SSTR)
#define STAGE_EL (2*A_EL + 2*B_EL)
#define STAGE_B  (STAGE_EL*2)

__global__ __launch_bounds__(256) void mma_gemm(
    const __nv_bfloat16* __restrict__ Ah, const __nv_bfloat16* __restrict__ Al,
    const __nv_bfloat16* __restrict__ Bh, const __nv_bfloat16* __restrict__ Bl,
    const float* __restrict__ bias, float* __restrict__ Cf,
    __nv_bfloat16* __restrict__ Ch, __nv_bfloat16* __restrict__ Cl)
{
    extern __shared__ __align__(16) __nv_bfloat16 sm[];

    const int tid  = threadIdx.x;
    const int wid  = tid >> 5;
    const int lane = tid & 31;
    const int bm = blockIdx.y * 128;
    const int bn = blockIdx.x * 256;
    const int wm = (wid & 1) * 64;
    const int wn = (wid >> 1) * 64;

    const uint32_t sb = smem_u32(sm);

    const int aOff = ((wm + (lane & 15)) * SSTR + (lane >> 4) * 8) * 2;
    const int bn_local = ((lane >> 4) & 1) * 8 + (lane & 7);
    const int bk_local = ((lane >> 3) & 1) * 8;
    const int bOff = ((wn + bn_local) * SSTR + bk_local) * 2;

    const int lrow = tid >> 2;
    const int lsege = (tid & 3) * 8;
    const uint32_t lso = (uint32_t)(lrow * SSTR + lsege) * 2;

    auto prefetch = [&](int j) {
        const int k0 = j * KST;
        const uint32_t st = sb + (j & 1) * STAGE_B;
        #pragma unroll
        for (int it = 0; it < 2; it++) {
            const int row = lrow + it * 64;
            const size_t g = (size_t)(bm + row) * DIM + k0 + lsege;
            const uint32_t d = st + (uint32_t)(it * 64 * SSTR * 2) + lso;
            cp16(d,              Ah + g);
            cp16(d + A_EL * 2,   Al + g);
        }
        #pragma unroll
        for (int it = 0; it < 4; it++) {
            const int row = lrow + it * 64;
            const size_t g = (size_t)(bn + row) * DIM + k0 + lsege;
            const uint32_t d = st + (uint32_t)(2 * A_EL * 2) + (uint32_t)(it * 64 * SSTR * 2) + lso;
            cp16(d,              Bh + g);
            cp16(d + B_EL * 2,   Bl + g);
        }
    };

    float acc[4][8][4];
    #pragma unroll
    for (int i = 0; i < 4; i++)
        #pragma unroll
        for (int j = 0; j < 8; j++)
            #pragma unroll
            for (int r = 0; r < 4; r++) acc[i][j][r] = 0.f;

    prefetch(0);
    cp_commit();

    for (int j = 0; j < DIM / KST; j++) {
        if (j + 1 < DIM / KST) {
            prefetch(j + 1);
            cp_commit();
            cp_wait<1>();
        } else {
            cp_wait<0>();
        }
        __syncthreads();

        const uint32_t st  = sb + (j & 1) * STAGE_B;
        const uint32_t aHi = st + aOff;
        const uint32_t aLo = aHi + A_EL * 2;
        const uint32_t bHi = st + 2 * A_EL * 2 + bOff;
        const uint32_t bLo = bHi + B_EL * 2;

        #pragma unroll
        for (int kk = 0; kk < KST / 16; kk++) {
            const uint32_t kb = kk * 32;
            uint32_t ah[4][4], al[4][4];
            #pragma unroll
            for (int mt = 0; mt < 4; mt++) {
                const uint32_t adr = mt * (16 * SSTR * 2) + kb;
                ldm_x4(aHi + adr, ah[mt][0], ah[mt][1], ah[mt][2], ah[mt][3]);
                ldm_x4(aLo + adr, al[mt][0], al[mt][1], al[mt][2], al[mt][3]);
            }
            #pragma unroll
            for (int h = 0; h < 2; h++) {
                uint32_t bh4[4][2], bl4[4][2];
                #pragma unroll
                for (int p = 0; p < 2; p++) {
                    const uint32_t adr = (h * 2 + p) * (16 * SSTR * 2) + kb;
                    ldm_x4(bHi + adr, bh4[p*2][0], bh4[p*2][1], bh4[p*2+1][0], bh4[p*2+1][1]);
                    ldm_x4(bLo + adr, bl4[p*2][0], bl4[p*2][1], bl4[p*2+1][0], bl4[p*2+1][1]);
                }
                #pragma unroll
                for (int mt = 0; mt < 4; mt++)
                    #pragma unroll
                    for (int q = 0; q < 4; q++) {
                        float* a = acc[mt][h*4 + q];
                        mma_bf16(a[0], a[1], a[2], a[3],
                                 ah[mt][0], ah[mt][1], ah[mt][2], ah[mt][3],
                                 bh4[q][0], bh4[q][1]);
                        mma_bf16(a[0], a[1], a[2], a[3],
                                 ah[mt][0], ah[mt][1], ah[mt][2], ah[mt][3],
                                 bl4[q][0], bl4[q][1]);
                        mma_bf16(a[0], a[1], a[2], a[3],
                                 al[mt][0], al[mt][1], al[mt][2], al[mt][3],
                                 bh4[q][0], bh4[q][1]);
                    }
            }
        }
        __syncthreads();
    }

    const int er = lane >> 2;
    const int ec = (lane & 3) * 2;
    #pragma unroll
    for (int mt = 0; mt < 4; mt++) {
        #pragma unroll
        for (int nt = 0; nt < 8; nt++) {
            const int col = bn + wn + nt * 8 + ec;
            const int r0  = bm + wm + mt * 16 + er;
            float x0 = acc[mt][nt][0], y0 = acc[mt][nt][1];
            float x1 = acc[mt][nt][2], y1 = acc[mt][nt][3];
            if (Cf) {
                float b0 = 0.f, b1 = 0.f;
                if (bias) { b0 = bias[col]; b1 = bias[col + 1]; }
                *(float2*)(Cf + (size_t)r0 * DIM + col)       = make_float2(x0 + b0, y0 + b1);
                *(float2*)(Cf + (size_t)(r0 + 8) * DIM + col) = make_float2(x1 + b0, y1 + b1);
            }
            if (Ch) {
                *(uint32_t*)(Ch + (size_t)r0 * DIM + col)       = pk2(x0, y0);
                *(uint32_t*)(Cl + (size_t)r0 * DIM + col)       = pk2(bf_lo(x0), bf_lo(y0));
                *(uint32_t*)(Ch + (size_t)(r0 + 8) * DIM + col) = pk2(x1, y1);
                *(uint32_t*)(Cl + (size_t)(r0 + 8) * DIM + col) = pk2(bf_lo(x1), bf_lo(y1));
            }
        }
    }
}

// =================== HMMA flash attention v3 ===================
// Round-12 structure (static 37KB smem union, sync tile fill), pre-split bf16 inputs.
// smem union (bf16 el, stride 72):
//   Q phase : Qh @0 (128x72=9216el), Ql @9216el
//   KV phase: Kh @0, Kl @4608el, Vh @9216el, Vl @13824el
#define ASTR 72

__global__ __launch_bounds__(256, 1) void attn_mma(
    const __nv_bfloat16* __restrict__ Qh_g, const __nv_bfloat16* __restrict__ Ql_g,
    const __nv_bfloat16* __restrict__ Kh_g, const __nv_bfloat16* __restrict__ Kl_g,
    const __nv_bfloat16* __restrict__ Vh_g, const __nv_bfloat16* __restrict__ Vl_g,
    const float* __restrict__ Qf, const float* __restrict__ XKf, const float* __restrict__ XVf,
    __nv_bfloat16* __restrict__ AOh, __nv_bfloat16* __restrict__ AOl)
{
    __shared__ __align__(16) __nv_bfloat16 sbuf[18432];
    __shared__ float sdiag[128];

    const int tid = threadIdx.x, wid = tid >> 5, lane = tid & 31;
    const int er = lane >> 2, ec = lane & 3;
    const int b  = blockIdx.y >> 3, h = blockIdx.y & 7;
    const int q0 = blockIdx.x * 128;

    const uint32_t sb = smem_u32(sbuf);

    // ---- Q tile: bf16 hi/lo direct copy into smem ----
    {
        const int row = tid >> 1, half = tid & 1;
        const size_t g = (size_t)(b*SEQ + q0 + row)*DIM + h*DH + half*32;
        __nv_bfloat16* dh = sbuf + row*ASTR + half*32;
        __nv_bfloat16* dl = dh + 9216;
        #pragma unroll
        for (int c = 0; c < 4; c++) {
            *(uint4*)(dh + c*8) = *(const uint4*)(Qh_g + g + c*8);
            *(uint4*)(dl + c*8) = *(const uint4*)(Ql_g + g + c*8);
        }
    }

    // ---- diagonal logit: dl = 0.125 * dot(q_row, xk_row) ----
    {
        const int rl = lane >> 1, half = lane & 1;
        const size_t g = (size_t)(b*SEQ + q0 + wid*16 + rl)*DIM + h*DH + half*32;
        const float* qd = Qf  + g;
        const float* xd = XKf + g;
        float dl = 0.f;
        #pragma unroll
        for (int i = 0; i < 8; i++) {
            float4 a = *(const float4*)(qd + i*4);
            float4 c = *(const float4*)(xd + i*4);
            dl = fmaf(a.x, c.x, fmaf(a.y, c.y, fmaf(a.z, c.z, fmaf(a.w, c.w, dl))));
        }
        dl += __shfl_xor_sync(0xffffffffu, dl, 1);
        if (half == 0) sdiag[wid*16 + rl] = dl * 0.125f;
    }
    __syncthreads();

    // ---- Q A-fragments (resident across whole kv loop) ----
    uint32_t aqh[4][4], aql[4][4];
    {
        const uint32_t ao = (uint32_t)(((wid*16 + (lane & 15))*ASTR + (lane >> 4)*8) * 2);
        #pragma unroll
        for (int kt = 0; kt < 4; kt++) {
            ldm_x4(sb + ao + kt*32,         aqh[kt][0], aqh[kt][1], aqh[kt][2], aqh[kt][3]);
            ldm_x4(sb + 18432 + ao + kt*32, aql[kt][0], aql[kt][1], aql[kt][2], aql[kt][3]);
        }
    }

    float m0 = -1e30f, m1 = -1e30f, l0s = 0.f, l1s = 0.f;
    float o[8][4];
    #pragma unroll
    for (int i = 0; i < 8; i++)
        #pragma unroll
        for (int j = 0; j < 4; j++) o[i][j] = 0.f;

    const uint32_t bKoff = (uint32_t)(((((lane>>4)&1)*8 + (lane&7))*ASTR + ((lane>>3)&1)*8) * 2);
    const int vm = lane >> 3;
    const uint32_t vOff = (uint32_t)((((vm&1)*8 + (lane&7))*ASTR + (vm>>1)*8) * 2);

    const int kvrow = tid >> 2, kvc = (tid & 3) * 16;

    for (int t = 0; t < SEQ/64; t++) {
        __syncthreads();
        // ---- K/V tile: bf16 hi/lo direct copy ----
        {
            const size_t g = (size_t)(b*SEQ + t*64 + kvrow)*DIM + h*DH + kvc;
            __nv_bfloat16* d0 = sbuf + kvrow*ASTR + kvc;
            #pragma unroll
            for (int c = 0; c < 2; c++) {
                *(uint4*)(d0 + c*8)         = *(const uint4*)(Kh_g + g + c*8);
                *(uint4*)(d0 + 4608  + c*8) = *(const uint4*)(Kl_g + g + c*8);
                *(uint4*)(d0 + 9216  + c*8) = *(const uint4*)(Vh_g + g + c*8);
                *(uint4*)(d0 + 13824 + c*8) = *(const uint4*)(Vl_g + g + c*8);
            }
        }
        __syncthreads();

        // ---- S = Q K^T (3-pass compensated) ----
        float s[8][4];
        #pragma unroll
        for (int i = 0; i < 8; i++)
            #pragma unroll
            for (int j = 0; j < 4; j++) s[i][j] = 0.f;

        #pragma unroll
        for (int np = 0; np < 4; np++) {
            const uint32_t base = sb + bKoff + np*(16*ASTR*2);
            #pragma unroll
            for (int kt = 0; kt < 4; kt++) {
                uint32_t kh[4], kl[4];
                ldm_x4(base + kt*32,        kh[0], kh[1], kh[2], kh[3]);
                ldm_x4(base + 9216 + kt*32, kl[0], kl[1], kl[2], kl[3]);
                const int nt = np*2;
                mma_bf16(s[nt][0],s[nt][1],s[nt][2],s[nt][3],
                         aqh[kt][0],aqh[kt][1],aqh[kt][2],aqh[kt][3], kh[0],kh[1]);
                mma_bf16(s[nt][0],s[nt][1],s[nt][2],s[nt][3],
                         aqh[kt][0],aqh[kt][1],aqh[kt][2],aqh[kt][3], kl[0],kl[1]);
                mma_bf16(s[nt][0],s[nt][1],s[nt][2],s[nt][3],
                         aql[kt][0],aql[kt][1],aql[kt][2],aql[kt][3], kh[0],kh[1]);
                mma_bf16(s[nt+1][0],s[nt+1][1],s[nt+1][2],s[nt+1][3],
                         aqh[kt][0],aqh[kt][1],aqh[kt][2],aqh[kt][3], kh[2],kh[3]);
                mma_bf16(s[nt+1][0],s[nt+1][1],s[nt+1][2],s[nt+1][3],
                         aqh[kt][0],aqh[kt][1],aqh[kt][2],aqh[kt][3], kl[2],kl[3]);
                mma_bf16(s[nt+1][0],s[nt+1][1],s[nt+1][2],s[nt+1][3],
                         aql[kt][0],aql[kt][1],aql[kt][2],aql[kt][3], kh[2],kh[3]);
            }
        }

        // ---- scale + online softmax ----
        float rm0 = -1e30f, rm1 = -1e30f;
        #pragma unroll
        for (int nt = 0; nt < 8; nt++) {
            s[nt][0] *= 0.125f; s[nt][1] *= 0.125f;
            s[nt][2] *= 0.125f; s[nt][3] *= 0.125f;
            rm0 = fmaxf(rm0, fmaxf(s[nt][0], s[nt][1]));
            rm1 = fmaxf(rm1, fmaxf(s[nt][2], s[nt][3]));
        }
        rm0 = fmaxf(rm0, __shfl_xor_sync(0xffffffffu, rm0, 1));
        rm0 = fmaxf(rm0, __shfl_xor_sync(0xffffffffu, rm0, 2));
        rm1 = fmaxf(rm1, __shfl_xor_sync(0xffffffffu, rm1, 1));
        rm1 = fmaxf(rm1, __shfl_xor_sync(0xffffffffu, rm1, 2));
        const float mn0 = fmaxf(m0, rm0), mn1 = fmaxf(m1, rm1);
        const float c0f = __expf(m0 - mn0), c1f = __expf(m1 - mn1);
        float ps0 = 0.f, ps1 = 0.f;
        #pragma unroll
        for (int nt = 0; nt < 8; nt++) {
            s[nt][0] = __expf(s[nt][0] - mn0); ps0 += s[nt][0];
            s[nt][1] = __expf(s[nt][1] - mn0); ps0 += s[nt][1];
            s[nt][2] = __expf(s[nt][2] - mn1); ps1 += s[nt][2];
            s[nt][3] = __expf(s[nt][3] - mn1); ps1 += s[nt][3];
        }
        ps0 += __shfl_xor_sync(0xffffffffu, ps0, 1);
        ps0 += __shfl_xor_sync(0xffffffffu, ps0, 2);
        ps1 += __shfl_xor_sync(0xffffffffu, ps1, 1);
        ps1 += __shfl_xor_sync(0xffffffffu, ps1, 2);
        l0s = l0s*c0f + ps0; l1s = l1s*c1f + ps1;
        m0 = mn0; m1 = mn1;
        #pragma unroll
        for (int nt = 0; nt < 8; nt++) {
            o[nt][0] *= c0f; o[nt][1] *= c0f;
            o[nt][2] *= c1f; o[nt][3] *= c1f;
        }

        // ---- P -> A fragments (FA2 register trick), hi/lo ----
        uint32_t ph[4][4], pl[4][4];
        #pragma unroll
        for (int kt = 0; kt < 4; kt++) {
            const int nt = 2*kt, np1 = 2*kt + 1;
            ph[kt][0] = pk2(s[nt][0],  s[nt][1]);
            ph[kt][1] = pk2(s[nt][2],  s[nt][3]);
            ph[kt][2] = pk2(s[np1][0], s[np1][1]);
            ph[kt][3] = pk2(s[np1][2], s[np1][3]);
            pl[kt][0] = pk2(bf_lo(s[nt][0]),  bf_lo(s[nt][1]));
            pl[kt][1] = pk2(bf_lo(s[nt][2]),  bf_lo(s[nt][3]));
            pl[kt][2] = pk2(bf_lo(s[np1][0]), bf_lo(s[np1][1]));
            pl[kt][3] = pk2(bf_lo(s[np1][2]), bf_lo(s[np1][3]));
        }

        // ---- O += P V (trans V, 3-pass) ----
        #pragma unroll
        for (int np = 0; np < 4; np++) {
            #pragma unroll
            for (int kt = 0; kt < 4; kt++) {
                uint32_t vh[4], vl[4];
                const uint32_t va = sb + 18432 + vOff + kt*(16*ASTR*2) + np*32;
                ldm_x4_t(va,        vh[0], vh[1], vh[2], vh[3]);
                ldm_x4_t(va + 9216, vl[0], vl[1], vl[2], vl[3]);
                const int nt = np*2;
                mma_bf16(o[nt][0],o[nt][1],o[nt][2],o[nt][3],
                         ph[kt][0],ph[kt][1],ph[kt][2],ph[kt][3], vh[0],vh[1]);
                mma_bf16(o[nt][0],o[nt][1],o[nt][2],o[nt][3],
                         ph[kt][0],ph[kt][1],ph[kt][2],ph[kt][3], vl[0],vl[1]);
                mma_bf16(o[nt][0],o[nt][1],o[nt][2],o[nt][3],
                         pl[kt][0],pl[kt][1],pl[kt][2],pl[kt][3], vh[0],vh[1]);
                mma_bf16(o[nt+1][0],o[nt+1][1],o[nt+1][2],o[nt+1][3],
                         ph[kt][0],ph[kt][1],ph[kt][2],ph[kt][3], vh[2],vh[3]);
                mma_bf16(o[nt+1][0],o[nt+1][1],o[nt+1][2],o[nt+1][3],
                         ph[kt][0],ph[kt][1],ph[kt][2],ph[kt][3], vl[2],vl[3]);
                mma_bf16(o[nt+1][0],o[nt+1][1],o[nt+1][2],o[nt+1][3],
                         pl[kt][0],pl[kt][1],pl[kt][2],pl[kt][3], vh[2],vh[3]);
            }
        }
    }

    const float dl0 = sdiag[wid*16 + er];
    const float dl1 = sdiag[wid*16 + er + 8];

    // ---- merge diag + finalize + store bf16 hi/lo ----
    {
        const float mn0 = fmaxf(m0, dl0), mn1 = fmaxf(m1, dl1);
        const float c0f = __expf(m0 - mn0), c1f = __expf(m1 - mn1);
        const float pd0 = __expf(dl0 - mn0), pd1 = __expf(dl1 - mn1);
        const float inv0 = 1.0f / (l0s*c0f + pd0);
        const float inv1 = 1.0f / (l1s*c1f + pd1);
        const size_t gr0 = (size_t)(b*SEQ + q0 + wid*16 + er);
        const size_t gr1 = gr0 + 8;
        #pragma unroll
        for (int nt = 0; nt < 8; nt++) {
            const int col = h*DH + nt*8 + ec*2;
            float2 xv0 = *(const float2*)(XVf + gr0*DIM + col);
            float2 xv1 = *(const float2*)(XVf + gr1*DIM + col);
            float ox0 = (o[nt][0]*c0f + pd0*xv0.x) * inv0;
            float oy0 = (o[nt][1]*c0f + pd0*xv0.y) * inv0;
            float ox1 = (o[nt][2]*c1f + pd1*xv1.x) * inv1;
            float oy1 = (o[nt][3]*c1f + pd1*xv1.y) * inv1;
            unsigned ha,hb,la,lb;
            bf16_split(ox0, ha, la); bf16_split(oy0, hb, lb);
            *(uint32_t*)(AOh + gr0*DIM + col) = ha | (hb<<16);
            *(uint32_t*)(AOl + gr0*DIM + col) = la | (lb<<16);
            bf16_split(ox1, ha, la); bf16_split(oy1, hb, lb);
            *(uint32_t*)(AOh + gr1*DIM + col) = ha | (hb<<16);
            *(uint32_t*)(AOl + gr1*DIM + col) = la | (lb<<16);
        }
    }
}

// =================== launch ===================
extern "C" void kernel_launch(void* const* d_in, const int* in_sizes, int n_in,
                              void* d_out, int out_size)
{
    const float* xq = (const float*)d_in[0];
    const float* xk = (const float*)d_in[1];
    const float* xv = (const float*)d_in[2];
    const float* Wq = (const float*)d_in[3];
    const float* Wk = (const float*)d_in[4];
    const float* Wv = (const float*)d_in[5];
    const float* Wo = (const float*)d_in[6];
    const float* bo = (const float*)d_in[7];
    float* out = (float*)d_out;

    float *Qp, *XKp, *XVp;
    cudaGetSymbolAddress((void**)&Qp,  g_Q);
    cudaGetSymbolAddress((void**)&XKp, g_XK);
    cudaGetSymbolAddress((void**)&XVp, g_XV);

    __nv_bfloat16 *xqh,*xql,*xkh,*xkl,*xvh,*xvl,*aoh,*aol;
    __nv_bfloat16 *qh,*ql,*kh,*kl,*vh,*vl;
    __nv_bfloat16 *wqh,*wql,*wkh,*wkl,*wvh,*wvl,*woh,*wol;
    cudaGetSymbolAddress((void**)&xqh, g_xqh); cudaGetSymbolAddress((void**)&xql, g_xql);
    cudaGetSymbolAddress((void**)&xkh, g_xkh); cudaGetSymbolAddress((void**)&xkl, g_xkl);
    cudaGetSymbolAddress((void**)&xvh, g_xvh); cudaGetSymbolAddress((void**)&xvl, g_xvl);
    cudaGetSymbolAddress((void**)&aoh, g_AOh); cudaGetSymbolAddress((void**)&aol, g_AOl);
    cudaGetSymbolAddress((void**)&qh,  g_Qh);  cudaGetSymbolAddress((void**)&ql,  g_Ql);
    cudaGetSymbolAddress((void**)&kh,  g_Kh);  cudaGetSymbolAddress((void**)&kl,  g_Kl);
    cudaGetSymbolAddress((void**)&vh,  g_Vh);  cudaGetSymbolAddress((void**)&vl,  g_Vl);
    cudaGetSymbolAddress((void**)&wqh, g_WqTh); cudaGetSymbolAddress((void**)&wql, g_WqTl);
    cudaGetSymbolAddress((void**)&wkh, g_WkTh); cudaGetSymbolAddress((void**)&wkl, g_WkTl);
    cudaGetSymbolAddress((void**)&wvh, g_WvTh); cudaGetSymbolAddress((void**)&wvl, g_WvTl);
    cudaGetSymbolAddress((void**)&woh, g_WoTh); cudaGetSymbolAddress((void**)&wol, g_WoTl);

    const int gemm_smem = 2 * STAGE_B;
    cudaFuncSetAttribute(mma_gemm,
                         cudaFuncAttributeMaxDynamicSharedMemorySize, gemm_smem);

    // ---- conversions ----
    const int n4 = MROWS*DIM/4;
    split_hl<<<n4/256, 256>>>((const float4*)xq, (uint2*)xqh, (uint2*)xql, n4);
    split_hl<<<n4/256, 256>>>((const float4*)xk, (uint2*)xkh, (uint2*)xkl, n4);
    split_hl<<<n4/256, 256>>>((const float4*)xv, (uint2*)xvh, (uint2*)xvl, n4);
    dim3 tgrid(DIM/32, DIM/32), tblk(32, 32);
    splitT<<<tgrid, tblk>>>(Wq, wqh, wql);
    splitT<<<tgrid, tblk>>>(Wk, wkh, wkl);
    splitT<<<tgrid, tblk>>>(Wv, wvh, wvl);
    splitT<<<tgrid, tblk>>>(Wo, woh, wol);

    // ---- projection GEMMs ----
    dim3 gg(DIM/256, MROWS/128);
    mma_gemm<<<gg, 256, gemm_smem>>>(xqh, xql, wqh, wql, nullptr, Qp,      qh, ql);
    mma_gemm<<<gg, 256, gemm_smem>>>(xkh, xkl, wkh, wkl, nullptr, nullptr, kh, kl);
    mma_gemm<<<gg, 256, gemm_smem>>>(xvh, xvl, wvh, wvl, nullptr, nullptr, vh, vl);
    mma_gemm<<<gg, 256, gemm_smem>>>(xqh, xql, wkh, wkl, nullptr, XKp,     nullptr, nullptr);
    mma_gemm<<<gg, 256, gemm_smem>>>(xqh, xql, wvh, wvl, nullptr, XVp,     nullptr, nullptr);

    // ---- HMMA attention (round-12 structure, bf16 inputs) ----
    dim3 ga(SEQ/128, NB*NH);       // (16, 32)
    attn_mma<<<ga, 256>>>(qh, ql, kh, kl, vh, vl, Qp, XKp, XVp, aoh, aol);

    // ---- output GEMM (+bias) ----
    mma_gemm<<<gg, 256, gemm_smem>>>(aoh, aol, woh, wol, bo, out, nullptr, nullptr);
}

// round 17
// speedup vs baseline: 1.4830x; 1.4830x over previous
#include <cuda_runtime.h>
#include <cuda_bf16.h>
#include <cstdint>
#include <math.h>

#define NB   4
#define NH   8
#define SEQ  2048
#define DIM  512
#define DH   64
#define MROWS (NB*SEQ)   // 8192

// =================== scratch (static device globals) ===================
__device__ float g_Q [MROWS*DIM];
__device__ float g_K [MROWS*DIM];
__device__ float g_V [MROWS*DIM];
__device__ float g_XK[MROWS*DIM];
__device__ float g_XV[MROWS*DIM];

__device__ __align__(16) __nv_bfloat16 g_xqh[MROWS*DIM], g_xql[MROWS*DIM];
__device__ __align__(16) __nv_bfloat16 g_xkh[MROWS*DIM], g_xkl[MROWS*DIM];
__device__ __align__(16) __nv_bfloat16 g_xvh[MROWS*DIM], g_xvl[MROWS*DIM];
__device__ __align__(16) __nv_bfloat16 g_AOh[MROWS*DIM], g_AOl[MROWS*DIM];

__device__ __align__(16) __nv_bfloat16 g_Qh [MROWS*DIM], g_Ql [MROWS*DIM];
__device__ __align__(16) __nv_bfloat16 g_Kh [MROWS*DIM], g_Kl [MROWS*DIM];
__device__ __align__(16) __nv_bfloat16 g_Vh [MROWS*DIM], g_Vl [MROWS*DIM];

__device__ __align__(16) __nv_bfloat16 g_WqTh[DIM*DIM], g_WqTl[DIM*DIM];
__device__ __align__(16) __nv_bfloat16 g_WkTh[DIM*DIM], g_WkTl[DIM*DIM];
__device__ __align__(16) __nv_bfloat16 g_WvTh[DIM*DIM], g_WvTl[DIM*DIM];
__device__ __align__(16) __nv_bfloat16 g_WoTh[DIM*DIM], g_WoTl[DIM*DIM];

// =================== helpers ===================
__device__ __forceinline__ uint32_t smem_u32(const void* p) {
    uint32_t a;
    asm("{ .reg .u64 t; cvta.to.shared.u64 t, %1; cvt.u32.u64 %0, t; }" : "=r"(a) : "l"(p));
    return a;
}

__device__ __forceinline__ void ldm_x4(uint32_t addr, uint32_t& r0, uint32_t& r1,
                                       uint32_t& r2, uint32_t& r3) {
    asm volatile("ldmatrix.sync.aligned.m8n8.x4.shared.b16 {%0,%1,%2,%3}, [%4];"
                 : "=r"(r0), "=r"(r1), "=r"(r2), "=r"(r3) : "r"(addr));
}
__device__ __forceinline__ void ldm_x4_t(uint32_t addr, uint32_t& r0, uint32_t& r1,
                                         uint32_t& r2, uint32_t& r3) {
    asm volatile("ldmatrix.sync.aligned.m8n8.x4.trans.shared.b16 {%0,%1,%2,%3}, [%4];"
                 : "=r"(r0), "=r"(r1), "=r"(r2), "=r"(r3) : "r"(addr));
}

__device__ __forceinline__ void mma_bf16(float& c0, float& c1, float& c2, float& c3,
                                         uint32_t a0, uint32_t a1, uint32_t a2, uint32_t a3,
                                         uint32_t b0, uint32_t b1) {
    asm volatile(
        "mma.sync.aligned.m16n8k16.row.col.f32.bf16.bf16.f32 "
        "{%0,%1,%2,%3}, {%4,%5,%6,%7}, {%8,%9}, {%0,%1,%2,%3};"
        : "+f"(c0), "+f"(c1), "+f"(c2), "+f"(c3)
        : "r"(a0), "r"(a1), "r"(a2), "r"(a3), "r"(b0), "r"(b1));
}

__device__ __forceinline__ void cp16(uint32_t dst, const void* src) {
    asm volatile("cp.async.cg.shared.global [%0], [%1], 16;" :: "r"(dst), "l"(src));
}
__device__ __forceinline__ void cp_commit() {
    asm volatile("cp.async.commit_group;");
}
template<int N> __device__ __forceinline__ void cp_wait() {
    asm volatile("cp.async.wait_group %0;" :: "n"(N));
}

__device__ __forceinline__ void bf16_split(float x, unsigned& h, unsigned& l) {
    __nv_bfloat16 bh = __float2bfloat16_rn(x);
    float r = x - __bfloat162float(bh);
    __nv_bfloat16 bl = __float2bfloat16_rn(r);
    h = (unsigned)__bfloat16_as_ushort(bh);
    l = (unsigned)__bfloat16_as_ushort(bl);
}
__device__ __forceinline__ float bf_lo(float x) {
    return x - __bfloat162float(__float2bfloat16_rn(x));
}
__device__ __forceinline__ uint32_t pk2(float a, float b) {
    return (uint32_t)__bfloat16_as_ushort(__float2bfloat16_rn(a)) |
           ((uint32_t)__bfloat16_as_ushort(__float2bfloat16_rn(b)) << 16);
}

// =================== conversion kernels ===================
__global__ __launch_bounds__(256) void split_hl(
    const float4* __restrict__ in, uint2* __restrict__ hi, uint2* __restrict__ lo, int n4)
{
    int i = blockIdx.x * 256 + threadIdx.x;
    if (i >= n4) return;
    float4 v = in[i];
    unsigned h0,h1,h2,h3,l0,l1,l2,l3;
    bf16_split(v.x, h0, l0); bf16_split(v.y, h1, l1);
    bf16_split(v.z, h2, l2); bf16_split(v.w, h3, l3);
    hi[i] = make_uint2(h0 | (h1 << 16), h2 | (h3 << 16));
    lo[i] = make_uint2(l0 | (l1 << 16), l2 | (l3 << 16));
}

__global__ __launch_bounds__(1024) void splitT(
    const float* __restrict__ W, __nv_bfloat16* __restrict__ hiT, __nv_bfloat16* __restrict__ loT)
{
    __shared__ float t[32][33];
    const int kb = blockIdx.y * 32, nb = blockIdx.x * 32;
    const int tx = threadIdx.x, ty = threadIdx.y;
    t[ty][tx] = W[(kb + ty) * DIM + nb + tx];
    __syncthreads();
    float x = t[tx][ty];
    unsigned h, l;
    bf16_split(x, h, l);
    hiT[(nb + ty) * DIM + kb + tx] = __ushort_as_bfloat16((unsigned short)h);
    loT[(nb + ty) * DIM + kb + tx] = __ushort_as_bfloat16((unsigned short)l);
}

// =================== HMMA GEMM (round-12 exact: single fp32 output) ===================
#define KST   32
#define SSTR  40
#define A_EL  (128*SSTR)
#define B_EL  (256*SSTR)
#define STAGE_EL (2*A_EL + 2*B_EL)
#define STAGE_B  (STAGE_EL*2)

__global__ __launch_bounds__(256) void mma_gemm(
    const __nv_bfloat16* __restrict__ Ah, const __nv_bfloat16* __restrict__ Al,
    const __nv_bfloat16* __restrict__ Bh, const __nv_bfloat16* __restrict__ Bl,
    const float* __restrict__ bias, float* __restrict__ C)
{
    extern __shared__ __align__(16) __nv_bfloat16 sm[];

    const int tid  = threadIdx.x;
    const int wid  = tid >> 5;
    const int lane = tid & 31;
    const int bm = blockIdx.y * 128;
    const int bn = blockIdx.x * 256;
    const int wm = (wid & 1) * 64;
    const int wn = (wid >> 1) * 64;

    const uint32_t sb = smem_u32(sm);

    const int aOff = ((wm + (lane & 15)) * SSTR + (lane >> 4) * 8) * 2;
    const int bn_local = ((lane >> 4) & 1) * 8 + (lane & 7);
    const int bk_local = ((lane >> 3) & 1) * 8;
    const int bOff = ((wn + bn_local) * SSTR + bk_local) * 2;

    const int lrow = tid >> 2;
    const int lsege = (tid & 3) * 8;
    const uint32_t lso = (uint32_t)(lrow * SSTR + lsege) * 2;

    auto prefetch = [&](int j) {
        const int k0 = j * KST;
        const uint32_t st = sb + (j & 1) * STAGE_B;
        #pragma unroll
        for (int it = 0; it < 2; it++) {
            const int row = lrow + it * 64;
            const size_t g = (size_t)(bm + row) * DIM + k0 + lsege;
            const uint32_t d = st + (uint32_t)(it * 64 * SSTR * 2) + lso;
            cp16(d,              Ah + g);
            cp16(d + A_EL * 2,   Al + g);
        }
        #pragma unroll
        for (int it = 0; it < 4; it++) {
            const int row = lrow + it * 64;
            const size_t g = (size_t)(bn + row) * DIM + k0 + lsege;
            const uint32_t d = st + (uint32_t)(2 * A_EL * 2) + (uint32_t)(it * 64 * SSTR * 2) + lso;
            cp16(d,              Bh + g);
            cp16(d + B_EL * 2,   Bl + g);
        }
    };

    float acc[4][8][4];
    #pragma unroll
    for (int i = 0; i < 4; i++)
        #pragma unroll
        for (int j = 0; j < 8; j++)
            #pragma unroll
            for (int r = 0; r < 4; r++) acc[i][j][r] = 0.f;

    prefetch(0);
    cp_commit();

    for (int j = 0; j < DIM / KST; j++) {
        if (j + 1 < DIM / KST) {
            prefetch(j + 1);
            cp_commit();
            cp_wait<1>();
        } else {
            cp_wait<0>();
        }
        __syncthreads();

        const uint32_t st  = sb + (j & 1) * STAGE_B;
        const uint32_t aHi = st + aOff;
        const uint32_t aLo = aHi + A_EL * 2;
        const uint32_t bHi = st + 2 * A_EL * 2 + bOff;
        const uint32_t bLo = bHi + B_EL * 2;

        #pragma unroll
        for (int kk = 0; kk < KST / 16; kk++) {
            const uint32_t kb = kk * 32;
            uint32_t ah[4][4], al[4][4];
            #pragma unroll
            for (int mt = 0; mt < 4; mt++) {
                const uint32_t adr = mt * (16 * SSTR * 2) + kb;
                ldm_x4(aHi + adr, ah[mt][0], ah[mt][1], ah[mt][2], ah[mt][3]);
                ldm_x4(aLo + adr, al[mt][0], al[mt][1], al[mt][2], al[mt][3]);
            }
            #pragma unroll
            for (int h = 0; h < 2; h++) {
                uint32_t bh4[4][2], bl4[4][2];
                #pragma unroll
                for (int p = 0; p < 2; p++) {
                    const uint32_t adr = (h * 2 + p) * (16 * SSTR * 2) + kb;
                    ldm_x4(bHi + adr, bh4[p*2][0], bh4[p*2][1], bh4[p*2+1][0], bh4[p*2+1][1]);
                    ldm_x4(bLo + adr, bl4[p*2][0], bl4[p*2][1], bl4[p*2+1][0], bl4[p*2+1][1]);
                }
                #pragma unroll
                for (int mt = 0; mt < 4; mt++)
                    #pragma unroll
                    for (int q = 0; q < 4; q++) {
                        float* a = acc[mt][h*4 + q];
                        mma_bf16(a[0], a[1], a[2], a[3],
                                 ah[mt][0], ah[mt][1], ah[mt][2], ah[mt][3],
                                 bh4[q][0], bh4[q][1]);
                        mma_bf16(a[0], a[1], a[2], a[3],
                                 ah[mt][0], ah[mt][1], ah[mt][2], ah[mt][3],
                                 bl4[q][0], bl4[q][1]);
                        mma_bf16(a[0], a[1], a[2], a[3],
                                 al[mt][0], al[mt][1], al[mt][2], al[mt][3],
                                 bh4[q][0], bh4[q][1]);
                    }
            }
        }
        __syncthreads();
    }

    const int er = lane >> 2;
    const int ec = (lane & 3) * 2;
    #pragma unroll
    for (int mt = 0; mt < 4; mt++) {
        #pragma unroll
        for (int nt = 0; nt < 8; nt++) {
            const int col = bn + wn + nt * 8 + ec;
            float b0 = 0.f, b1 = 0.f;
            if (bias) { b0 = bias[col]; b1 = bias[col + 1]; }
            const int r0 = bm + wm + mt * 16 + er;
            float2 v0 = make_float2(acc[mt][nt][0] + b0, acc[mt][nt][1] + b1);
            float2 v1 = make_float2(acc[mt][nt][2] + b0, acc[mt][nt][3] + b1);
            *(float2*)(C + (size_t)r0 * DIM + col)       = v0;
            *(float2*)(C + (size_t)(r0 + 8) * DIM + col) = v1;
        }
    }
}

// =================== HMMA flash attention (round-12 structure, pre-split bf16 inputs) ===================
#define ASTR 72

__global__ __launch_bounds__(256, 1) void attn_mma(
    const __nv_bfloat16* __restrict__ Qh_g, const __nv_bfloat16* __restrict__ Ql_g,
    const __nv_bfloat16* __restrict__ Kh_g, const __nv_bfloat16* __restrict__ Kl_g,
    const __nv_bfloat16* __restrict__ Vh_g, const __nv_bfloat16* __restrict__ Vl_g,
    const float* __restrict__ Qf, const float* __restrict__ XKf, const float* __restrict__ XVf,
    __nv_bfloat16* __restrict__ AOh, __nv_bfloat16* __restrict__ AOl)
{
    __shared__ __align__(16) __nv_bfloat16 sbuf[18432];
    __shared__ float sdiag[128];

    const int tid = threadIdx.x, wid = tid >> 5, lane = tid & 31;
    const int er = lane >> 2, ec = lane & 3;
    const int b  = blockIdx.y >> 3, h = blockIdx.y & 7;
    const int q0 = blockIdx.x * 128;

    const uint32_t sb = smem_u32(sbuf);

    // ---- Q tile: bf16 hi/lo direct copy into smem ----
    {
        const int row = tid >> 1, half = tid & 1;
        const size_t g = (size_t)(b*SEQ + q0 + row)*DIM + h*DH + half*32;
        __nv_bfloat16* dh = sbuf + row*ASTR + half*32;
        __nv_bfloat16* dl = dh + 9216;
        #pragma unroll
        for (int c = 0; c < 4; c++) {
            *(uint4*)(dh + c*8) = *(const uint4*)(Qh_g + g + c*8);
            *(uint4*)(dl + c*8) = *(const uint4*)(Ql_g + g + c*8);
        }
    }

    // ---- diagonal logit: dl = 0.125 * dot(q_row, xk_row) ----
    {
        const int rl = lane >> 1, half = lane & 1;
        const size_t g = (size_t)(b*SEQ + q0 + wid*16 + rl)*DIM + h*DH + half*32;
        const float* qd = Qf  + g;
        const float* xd = XKf + g;
        float dl = 0.f;
        #pragma unroll
        for (int i = 0; i < 8; i++) {
            float4 a = *(const float4*)(qd + i*4);
            float4 c = *(const float4*)(xd + i*4);
            dl = fmaf(a.x, c.x, fmaf(a.y, c.y, fmaf(a.z, c.z, fmaf(a.w, c.w, dl))));
        }
        dl += __shfl_xor_sync(0xffffffffu, dl, 1);
        if (half == 0) sdiag[wid*16 + rl] = dl * 0.125f;
    }
    __syncthreads();

    // ---- Q A-fragments (resident across whole kv loop) ----
    uint32_t aqh[4][4], aql[4][4];
    {
        const uint32_t ao = (uint32_t)(((wid*16 + (lane & 15))*ASTR + (lane >> 4)*8) * 2);
        #pragma unroll
        for (int kt = 0; kt < 4; kt++) {
            ldm_x4(sb + ao + kt*32,         aqh[kt][0], aqh[kt][1], aqh[kt][2], aqh[kt][3]);
            ldm_x4(sb + 18432 + ao + kt*32, aql[kt][0], aql[kt][1], aql[kt][2], aql[kt][3]);
        }
    }

    float m0 = -1e30f, m1 = -1e30f, l0s = 0.f, l1s = 0.f;
    float o[8][4];
    #pragma unroll
    for (int i = 0; i < 8; i++)
        #pragma unroll
        for (int j = 0; j < 4; j++) o[i][j] = 0.f;

    const uint32_t bKoff = (uint32_t)(((((lane>>4)&1)*8 + (lane&7))*ASTR + ((lane>>3)&1)*8) * 2);
    const int vm = lane >> 3;
    const uint32_t vOff = (uint32_t)((((vm&1)*8 + (lane&7))*ASTR + (vm>>1)*8) * 2);

    const int kvrow = tid >> 2, kvc = (tid & 3) * 16;

    for (int t = 0; t < SEQ/64; t++) {
        __syncthreads();
        // ---- K/V tile: bf16 hi/lo direct copy ----
        {
            const size_t g = (size_t)(b*SEQ + t*64 + kvrow)*DIM + h*DH + kvc;
            __nv_bfloat16* d0 = sbuf + kvrow*ASTR + kvc;
            #pragma unroll
            for (int c = 0; c < 2; c++) {
                *(uint4*)(d0 + c*8)         = *(const uint4*)(Kh_g + g + c*8);
                *(uint4*)(d0 + 4608  + c*8) = *(const uint4*)(Kl_g + g + c*8);
                *(uint4*)(d0 + 9216  + c*8) = *(const uint4*)(Vh_g + g + c*8);
                *(uint4*)(d0 + 13824 + c*8) = *(const uint4*)(Vl_g + g + c*8);
            }
        }
        __syncthreads();

        // ---- S = Q K^T (3-pass compensated) ----
        float s[8][4];
        #pragma unroll
        for (int i = 0; i < 8; i++)
            #pragma unroll
            for (int j = 0; j < 4; j++) s[i][j] = 0.f;

        #pragma unroll
        for (int np = 0; np < 4; np++) {
            const uint32_t base = sb + bKoff + np*(16*ASTR*2);
            #pragma unroll
            for (int kt = 0; kt < 4; kt++) {
                uint32_t kh[4], kl[4];
                ldm_x4(base + kt*32,        kh[0], kh[1], kh[2], kh[3]);
                ldm_x4(base + 9216 + kt*32, kl[0], kl[1], kl[2], kl[3]);
                const int nt = np*2;
                mma_bf16(s[nt][0],s[nt][1],s[nt][2],s[nt][3],
                         aqh[kt][0],aqh[kt][1],aqh[kt][2],aqh[kt][3], kh[0],kh[1]);
                mma_bf16(s[nt][0],s[nt][1],s[nt][2],s[nt][3],
                         aqh[kt][0],aqh[kt][1],aqh[kt][2],aqh[kt][3], kl[0],kl[1]);
                mma_bf16(s[nt][0],s[nt][1],s[nt][2],s[nt][3],
                         aql[kt][0],aql[kt][1],aql[kt][2],aql[kt][3], kh[0],kh[1]);
                mma_bf16(s[nt+1][0],s[nt+1][1],s[nt+1][2],s[nt+1][3],
                         aqh[kt][0],aqh[kt][1],aqh[kt][2],aqh[kt][3], kh[2],kh[3]);
                mma_bf16(s[nt+1][0],s[nt+1][1],s[nt+1][2],s[nt+1][3],
                         aqh[kt][0],aqh[kt][1],aqh[kt][2],aqh[kt][3], kl[2],kl[3]);
                mma_bf16(s[nt+1][0],s[nt+1][1],s[nt+1][2],s[nt+1][3],
                         aql[kt][0],aql[kt][1],aql[kt][2],aql[kt][3], kh[2],kh[3]);
            }
        }

        // ---- scale + online softmax ----
        float rm0 = -1e30f, rm1 = -1e30f;
        #pragma unroll
        for (int nt = 0; nt < 8; nt++) {
            s[nt][0] *= 0.125f; s[nt][1] *= 0.125f;
            s[nt][2] *= 0.125f; s[nt][3] *= 0.125f;
            rm0 = fmaxf(rm0, fmaxf(s[nt][0], s[nt][1]));
            rm1 = fmaxf(rm1, fmaxf(s[nt][2], s[nt][3]));
        }
        rm0 = fmaxf(rm0, __shfl_xor_sync(0xffffffffu, rm0, 1));
        rm0 = fmaxf(rm0, __shfl_xor_sync(0xffffffffu, rm0, 2));
        rm1 = fmaxf(rm1, __shfl_xor_sync(0xffffffffu, rm1, 1));
        rm1 = fmaxf(rm1, __shfl_xor_sync(0xffffffffu, rm1, 2));
        const float mn0 = fmaxf(m0, rm0), mn1 = fmaxf(m1, rm1);
        const float c0f = __expf(m0 - mn0), c1f = __expf(m1 - mn1);
        float ps0 = 0.f, ps1 = 0.f;
        #pragma unroll
        for (int nt = 0; nt < 8; nt++) {
            s[nt][0] = __expf(s[nt][0] - mn0); ps0 += s[nt][0];
            s[nt][1] = __expf(s[nt][1] - mn0); ps0 += s[nt][1];
            s[nt][2] = __expf(s[nt][2] - mn1); ps1 += s[nt][2];
            s[nt][3] = __expf(s[nt][3] - mn1); ps1 += s[nt][3];
        }
        ps0 += __shfl_xor_sync(0xffffffffu, ps0, 1);
        ps0 += __shfl_xor_sync(0xffffffffu, ps0, 2);
        ps1 += __shfl_xor_sync(0xffffffffu, ps1, 1);
        ps1 += __shfl_xor_sync(0xffffffffu, ps1, 2);
        l0s = l0s*c0f + ps0; l1s = l1s*c1f + ps1;
        m0 = mn0; m1 = mn1;
        #pragma unroll
        for (int nt = 0; nt < 8; nt++) {
            o[nt][0] *= c0f; o[nt][1] *= c0f;
            o[nt][2] *= c1f; o[nt][3] *= c1f;
        }

        // ---- P -> A fragments (FA2 register trick), hi/lo ----
        uint32_t ph[4][4], pl[4][4];
        #pragma unroll
        for (int kt = 0; kt < 4; kt++) {
            const int nt = 2*kt, np1 = 2*kt + 1;
            ph[kt][0] = pk2(s[nt][0],  s[nt][1]);
            ph[kt][1] = pk2(s[nt][2],  s[nt][3]);
            ph[kt][2] = pk2(s[np1][0], s[np1][1]);
            ph[kt][3] = pk2(s[np1][2], s[np1][3]);
            pl[kt][0] = pk2(bf_lo(s[nt][0]),  bf_lo(s[nt][1]));
            pl[kt][1] = pk2(bf_lo(s[nt][2]),  bf_lo(s[nt][3]));
            pl[kt][2] = pk2(bf_lo(s[np1][0]), bf_lo(s[np1][1]));
            pl[kt][3] = pk2(bf_lo(s[np1][2]), bf_lo(s[np1][3]));
        }

        // ---- O += P V (trans V, 3-pass) ----
        #pragma unroll
        for (int np = 0; np < 4; np++) {
            #pragma unroll
            for (int kt = 0; kt < 4; kt++) {
                uint32_t vh[4], vl[4];
                const uint32_t va = sb + 18432 + vOff + kt*(16*ASTR*2) + np*32;
                ldm_x4_t(va,        vh[0], vh[1], vh[2], vh[3]);
                ldm_x4_t(va + 9216, vl[0], vl[1], vl[2], vl[3]);
                const int nt = np*2;
                mma_bf16(o[nt][0],o[nt][1],o[nt][2],o[nt][3],
                         ph[kt][0],ph[kt][1],ph[kt][2],ph[kt][3], vh[0],vh[1]);
                mma_bf16(o[nt][0],o[nt][1],o[nt][2],o[nt][3],
                         ph[kt][0],ph[kt][1],ph[kt][2],ph[kt][3], vl[0],vl[1]);
                mma_bf16(o[nt][0],o[nt][1],o[nt][2],o[nt][3],
                         pl[kt][0],pl[kt][1],pl[kt][2],pl[kt][3], vh[0],vh[1]);
                mma_bf16(o[nt+1][0],o[nt+1][1],o[nt+1][2],o[nt+1][3],
                         ph[kt][0],ph[kt][1],ph[kt][2],ph[kt][3], vh[2],vh[3]);
                mma_bf16(o[nt+1][0],o[nt+1][1],o[nt+1][2],o[nt+1][3],
                         ph[kt][0],ph[kt][1],ph[kt][2],ph[kt][3], vl[2],vl[3]);
                mma_bf16(o[nt+1][0],o[nt+1][1],o[nt+1][2],o[nt+1][3],
                         pl[kt][0],pl[kt][1],pl[kt][2],pl[kt][3], vh[2],vh[3]);
            }
        }
    }

    const float dl0 = sdiag[wid*16 + er];
    const float dl1 = sdiag[wid*16 + er + 8];

    // ---- merge diag + finalize + store bf16 hi/lo ----
    {
        const float mn0 = fmaxf(m0, dl0), mn1 = fmaxf(m1, dl1);
        const float c0f = __expf(m0 - mn0), c1f = __expf(m1 - mn1);
        const float pd0 = __expf(dl0 - mn0), pd1 = __expf(dl1 - mn1);
        const float inv0 = 1.0f / (l0s*c0f + pd0);
        const float inv1 = 1.0f / (l1s*c1f + pd1);
        const size_t gr0 = (size_t)(b*SEQ + q0 + wid*16 + er);
        const size_t gr1 = gr0 + 8;
        #pragma unroll
        for (int nt = 0; nt < 8; nt++) {
            const int col = h*DH + nt*8 + ec*2;
            float2 xv0 = *(const float2*)(XVf + gr0*DIM + col);
            float2 xv1 = *(const float2*)(XVf + gr1*DIM + col);
            float ox0 = (o[nt][0]*c0f + pd0*xv0.x) * inv0;
            float oy0 = (o[nt][1]*c0f + pd0*xv0.y) * inv0;
            float ox1 = (o[nt][2]*c1f + pd1*xv1.x) * inv1;
            float oy1 = (o[nt][3]*c1f + pd1*xv1.y) * inv1;
            unsigned ha,hb,la,lb;
            bf16_split(ox0, ha, la); bf16_split(oy0, hb, lb);
            *(uint32_t*)(AOh + gr0*DIM + col) = ha | (hb<<16);
            *(uint32_t*)(AOl + gr0*DIM + col) = la | (lb<<16);
            bf16_split(ox1, ha, la); bf16_split(oy1, hb, lb);
            *(uint32_t*)(AOh + gr1*DIM + col) = ha | (hb<<16);
            *(uint32_t*)(AOl + gr1*DIM + col) = la | (lb<<16);
        }
    }
}

// =================== launch ===================
extern "C" void kernel_launch(void* const* d_in, const int* in_sizes, int n_in,
                              void* d_out, int out_size)
{
    const float* xq = (const float*)d_in[0];
    const float* xk = (const float*)d_in[1];
    const float* xv = (const float*)d_in[2];
    const float* Wq = (const float*)d_in[3];
    const float* Wk = (const float*)d_in[4];
    const float* Wv = (const float*)d_in[5];
    const float* Wo = (const float*)d_in[6];
    const float* bo = (const float*)d_in[7];
    float* out = (float*)d_out;

    float *Qp, *Kp, *Vp, *XKp, *XVp;
    cudaGetSymbolAddress((void**)&Qp,  g_Q);
    cudaGetSymbolAddress((void**)&Kp,  g_K);
    cudaGetSymbolAddress((void**)&Vp,  g_V);
    cudaGetSymbolAddress((void**)&XKp, g_XK);
    cudaGetSymbolAddress((void**)&XVp, g_XV);

    __nv_bfloat16 *xqh,*xql,*xkh,*xkl,*xvh,*xvl,*aoh,*aol;
    __nv_bfloat16 *qh,*ql,*kh,*kl,*vh,*vl;
    __nv_bfloat16 *wqh,*wql,*wkh,*wkl,*wvh,*wvl,*woh,*wol;
    cudaGetSymbolAddress((void**)&xqh, g_xqh); cudaGetSymbolAddress((void**)&xql, g_xql);
    cudaGetSymbolAddress((void**)&xkh, g_xkh); cudaGetSymbolAddress((void**)&xkl, g_xkl);
    cudaGetSymbolAddress((void**)&xvh, g_xvh); cudaGetSymbolAddress((void**)&xvl, g_xvl);
    cudaGetSymbolAddress((void**)&aoh, g_AOh); cudaGetSymbolAddress((void**)&aol, g_AOl);
    cudaGetSymbolAddress((void**)&qh,  g_Qh);  cudaGetSymbolAddress((void**)&ql,  g_Ql);
    cudaGetSymbolAddress((void**)&kh,  g_Kh);  cudaGetSymbolAddress((void**)&kl,  g_Kl);
    cudaGetSymbolAddress((void**)&vh,  g_Vh);  cudaGetSymbolAddress((void**)&vl,  g_Vl);
    cudaGetSymbolAddress((void**)&wqh, g_WqTh); cudaGetSymbolAddress((void**)&wql, g_WqTl);
    cudaGetSymbolAddress((void**)&wkh, g_WkTh); cudaGetSymbolAddress((void**)&wkl, g_WkTl);
    cudaGetSymbolAddress((void**)&wvh, g_WvTh); cudaGetSymbolAddress((void**)&wvl, g_WvTl);
    cudaGetSymbolAddress((void**)&woh, g_WoTh); cudaGetSymbolAddress((void**)&wol, g_WoTl);

    const int gemm_smem = 2 * STAGE_B;
    cudaFuncSetAttribute(mma_gemm,
                         cudaFuncAttributeMaxDynamicSharedMemorySize, gemm_smem);

    // ---- input conversions ----
    const int n4 = MROWS*DIM/4;
    split_hl<<<n4/256, 256>>>((const float4*)xq, (uint2*)xqh, (uint2*)xql, n4);
    split_hl<<<n4/256, 256>>>((const float4*)xk, (uint2*)xkh, (uint2*)xkl, n4);
    split_hl<<<n4/256, 256>>>((const float4*)xv, (uint2*)xvh, (uint2*)xvl, n4);
    dim3 tgrid(DIM/32, DIM/32), tblk(32, 32);
    splitT<<<tgrid, tblk>>>(Wq, wqh, wql);
    splitT<<<tgrid, tblk>>>(Wk, wkh, wkl);
    splitT<<<tgrid, tblk>>>(Wv, wvh, wvl);
    splitT<<<tgrid, tblk>>>(Wo, woh, wol);

    // ---- projection GEMMs (round-12 epilogue, fp32 out) ----
    dim3 gg(DIM/256, MROWS/128);
    mma_gemm<<<gg, 256, gemm_smem>>>(xqh, xql, wqh, wql, nullptr, Qp);
    mma_gemm<<<gg, 256, gemm_smem>>>(xkh, xkl, wkh, wkl, nullptr, Kp);
    mma_gemm<<<gg, 256, gemm_smem>>>(xvh, xvl, wvh, wvl, nullptr, Vp);
    mma_gemm<<<gg, 256, gemm_smem>>>(xqh, xql, wkh, wkl, nullptr, XKp);
    mma_gemm<<<gg, 256, gemm_smem>>>(xqh, xql, wvh, wvl, nullptr, XVp);

    // ---- standalone splits of Q/K/V for the attention kernel ----
    split_hl<<<n4/256, 256>>>((const float4*)Qp, (uint2*)qh, (uint2*)ql, n4);
    split_hl<<<n4/256, 256>>>((const float4*)Kp, (uint2*)kh, (uint2*)kl, n4);
    split_hl<<<n4/256, 256>>>((const float4*)Vp, (uint2*)vh, (uint2*)vl, n4);

    // ---- HMMA attention ----
    dim3 ga(SEQ/128, NB*NH);       // (16, 32)
    attn_mma<<<ga, 256>>>(qh, ql, kh, kl, vh, vl, Qp, XKp, XVp, aoh, aol);

    // ---- output GEMM (+bias) ----
    mma_gemm<<<gg, 256, gemm_smem>>>(aoh, aol, woh, wol, bo, out);
}